// round 16
// baseline (speedup 1.0000x reference)
#include <cuda_runtime.h>
#include <math.h>

#define NND 50000
#define NE  600000
#define HIDN 128

// ---------------- scratch (device globals; no allocation allowed) ----------
__device__ float g_Qh[NND * HIDN];
__device__ float g_Kh[NND * HIDN];
__device__ float g_Vh[NND * HIDN];
__device__ float g_conn_e[NE * HIDN];     // 307 MB
__device__ float g_p[NE * 8];
__device__ float g_ssum[NND * 8];
__device__ float g_agg[NND * HIDN];
__device__ float g_rowAcc[NND * HIDN];
__device__ float g_t1[NND * HIDN];
__device__ float g_t2[NND * HIDN];
__device__ float g_hA[NND * HIDN];
__device__ float g_hmid[NND * 256];

// ---------------- zero init (accumulators) ----------------------------------
__global__ void zero_kernel() {
    int gid = blockIdx.x * blockDim.x + threadIdx.x;
    int stride = gridDim.x * blockDim.x;
    for (int i = gid; i < NND * HIDN; i += stride) { g_agg[i] = 0.f; g_rowAcc[i] = 0.f; }
    for (int i = gid; i < NND * 8; i += stride) g_ssum[i] = 0.f;
}

// ---------------- generic SGEMM: C = A@B (+bias)(+res)(relu) ---------------
// BM=128, BN=128, BK=16, 256 threads, 8x8 per thread
template <bool RELU>
__global__ void __launch_bounds__(256) sgemm(
    const float* __restrict__ A, const float* __restrict__ B,
    const float* __restrict__ bias, const float* __restrict__ res,
    float* __restrict__ C, int M, int N, int K)
{
    __shared__ float As[16][132];
    __shared__ float Bs[16][128];
    int t = threadIdx.x;
    int bm0 = blockIdx.x * 128;
    int bn0 = blockIdx.y * 128;
    int ty = t >> 4, tx = t & 15;

    float acc[8][8];
#pragma unroll
    for (int i = 0; i < 8; i++)
#pragma unroll
        for (int j = 0; j < 8; j++) acc[i][j] = 0.f;

    for (int k0 = 0; k0 < K; k0 += 16) {
        // A tile: 128x16 = 512 float4
#pragma unroll
        for (int i = 0; i < 2; i++) {
            int idx = t + i * 256;
            int m = idx >> 2, kq = idx & 3;
            int row = bm0 + m; if (row >= M) row = M - 1;
            float4 v = *(const float4*)(A + (size_t)row * K + k0 + kq * 4);
            As[kq * 4 + 0][m] = v.x; As[kq * 4 + 1][m] = v.y;
            As[kq * 4 + 2][m] = v.z; As[kq * 4 + 3][m] = v.w;
        }
        // B tile: 16x128 = 512 float4
#pragma unroll
        for (int i = 0; i < 2; i++) {
            int idx = t + i * 256;
            int k = idx >> 5, nq = idx & 31;
            *(float4*)&Bs[k][nq * 4] =
                *(const float4*)(B + (size_t)(k0 + k) * N + bn0 + nq * 4);
        }
        __syncthreads();
#pragma unroll
        for (int kk = 0; kk < 16; kk++) {
            float a[8], b[8];
#pragma unroll
            for (int i = 0; i < 8; i++) a[i] = As[kk][ty * 8 + i];
#pragma unroll
            for (int j = 0; j < 8; j++) b[j] = Bs[kk][tx * 8 + j];
#pragma unroll
            for (int i = 0; i < 8; i++)
#pragma unroll
                for (int j = 0; j < 8; j++) acc[i][j] = fmaf(a[i], b[j], acc[i][j]);
        }
        __syncthreads();
    }
#pragma unroll
    for (int i = 0; i < 8; i++) {
        int r = bm0 + ty * 8 + i;
        if (r >= M) continue;
#pragma unroll
        for (int j = 0; j < 8; j++) {
            int cn = bn0 + tx * 8 + j;
            float v = acc[i][j];
            if (bias) v += bias[cn];
            if (res)  v += res[(size_t)r * N + cn];
            if (RELU) v = fmaxf(v, 0.f);
            C[(size_t)r * N + cn] = v;
        }
    }
}

// ---------------- edge kernel A: fused Eh GEMM + conn_e + score + ssum -----
// block = 64 edges x 256 cols of WE, 256 threads, 8x8 per thread
__global__ void __launch_bounds__(256) edge_kernelA(
    const float* __restrict__ conn, const float* __restrict__ WE,
    const float* __restrict__ Aw,
    const int* __restrict__ dst, const int* __restrict__ src)
{
    extern __shared__ float sm[];
    float* EhT = sm;                         // 64*256 floats (phase 2+)
    float (*As)[68]  = (float(*)[68])sm;     // phase 1 (overlaps EhT)
    float (*Bs)[256] = (float(*)[256])(sm + 16 * 68);
    float* AwS = sm + 16384;                 // 128
    int* dstS = (int*)(sm + 16384 + 128);    // 64
    int* srcS = (int*)(sm + 16384 + 128 + 64); // 64

    int t = threadIdx.x;
    int e0 = blockIdx.x * 64;

    if (t < 128) AwS[t] = Aw[t];
    else if (t < 192) dstS[t - 128] = dst[e0 + t - 128];
    else srcS[t - 192] = src[e0 + t - 192];
    __syncthreads();

    int ty = t >> 5, tx = t & 31;
    float acc[8][8];
#pragma unroll
    for (int i = 0; i < 8; i++)
#pragma unroll
        for (int j = 0; j < 8; j++) acc[i][j] = 0.f;

    for (int k0 = 0; k0 < 128; k0 += 16) {
        {   // A tile 64x16 = 256 float4
            int m = t >> 2, kq = t & 3;
            float4 v = *(const float4*)(conn + (size_t)(e0 + m) * 128 + k0 + kq * 4);
            As[kq * 4 + 0][m] = v.x; As[kq * 4 + 1][m] = v.y;
            As[kq * 4 + 2][m] = v.z; As[kq * 4 + 3][m] = v.w;
        }
#pragma unroll
        for (int i = 0; i < 4; i++) {  // B tile 16x256 = 1024 float4
            int idx = t + i * 256;
            int k = idx >> 6, nq = idx & 63;
            *(float4*)&Bs[k][nq * 4] =
                *(const float4*)(WE + (size_t)(k0 + k) * 256 + nq * 4);
        }
        __syncthreads();
#pragma unroll
        for (int kk = 0; kk < 16; kk++) {
            float a[8], b[8];
#pragma unroll
            for (int i = 0; i < 8; i++) a[i] = As[kk][ty * 8 + i];
#pragma unroll
            for (int j = 0; j < 8; j++) b[j] = Bs[kk][tx * 8 + j];
#pragma unroll
            for (int i = 0; i < 8; i++)
#pragma unroll
                for (int j = 0; j < 8; j++) acc[i][j] = fmaf(a[i], b[j], acc[i][j]);
        }
        __syncthreads();
    }
    // stash Eh tile (Ew | Eb) in shared
#pragma unroll
    for (int i = 0; i < 8; i++)
#pragma unroll
        for (int j = 0; j < 8; j++)
            EhT[(ty * 8 + i) * 256 + tx * 8 + j] = acc[i][j];
    __syncthreads();

    // conn_e = relu(signed_sqrt((Qh[dst]+Kh[src]) * Ew) + Eb)
#pragma unroll 4
    for (int it = 0; it < 32; it++) {
        int idx = it * 256 + t;
        int r = idx >> 7, c = idx & 127;
        int de = dstS[r], se = srcS[r];
        float m1 = g_Qh[de * 128 + c] + g_Kh[se * 128 + c];
        float ew = EhT[r * 256 + c];
        float eb = EhT[r * 256 + c + 128];
        float xv = m1 * ew;
        float ssv = xv > 0.f ? sqrtf(xv) : (xv < 0.f ? -sqrtf(-xv) : 0.f);
        float v = fmaxf(ssv + eb, 0.f);
        g_conn_e[(size_t)(e0 + r) * 128 + c] = v;
        EhT[r * 256 + c] = v;
    }
    __syncthreads();

    // per-(edge,head) score: clip, exp, atomic denominator
#pragma unroll
    for (int it = 0; it < 2; it++) {
        int task = it * 256 + t;
        int r = task >> 3, h = task & 7;
        float s = 0.f;
#pragma unroll
        for (int d = 0; d < 16; d++) s += EhT[r * 256 + h * 16 + d] * AwS[d * 8 + h];
        s = fminf(fmaxf(s, -5.f), 5.f);
        float p = expf(s);
        g_p[(e0 + r) * 8 + h] = p;
        atomicAdd(&g_ssum[dstS[r] * 8 + h], p);
    }
}

// ---------------- edge kernel B: normalize + segment-sum scatter -----------
// one thread per (edge, 4 columns): E*32 threads total, float4 loads
__global__ void __launch_bounds__(256) edge_kernelB(
    const int* __restrict__ dst, const int* __restrict__ src)
{
    int gid = blockIdx.x * 256 + threadIdx.x;   // E*32 total
    int e = gid >> 5, q = gid & 31;
    int c = q * 4;                 // 4 contiguous cols, all in head h
    int h = c >> 4;
    int de = dst[e], se = src[e];
    float p = g_p[e * 8 + h];
    float w = p / (g_ssum[de * 8 + h] + 1e-16f);
    float4 v  = *(const float4*)&g_Vh[se * 128 + c];
    float4 ce = *(const float4*)&g_conn_e[(size_t)e * 128 + c];
    float* aggp = &g_agg[de * 128 + c];
    float* rowp = &g_rowAcc[de * 128 + c];
    atomicAdd(aggp + 0, v.x * w);
    atomicAdd(aggp + 1, v.y * w);
    atomicAdd(aggp + 2, v.z * w);
    atomicAdd(aggp + 3, v.w * w);
    atomicAdd(rowp + 0, ce.x * w);
    atomicAdd(rowp + 1, ce.y * w);
    atomicAdd(rowp + 2, ce.z * w);
    atomicAdd(rowp + 3, ce.w * w);
}

// ---------------- node combine: rowV@Bw, h_attn, degree scaling ------------
__global__ void __launch_bounds__(128) combine_kernel(
    const float* __restrict__ log_deg, const float* __restrict__ deg_coef,
    const float* __restrict__ Bw)
{
    int n = blockIdx.x, c = threadIdx.x;
    __shared__ float rowS[128];
    rowS[c] = g_rowAcc[n * 128 + c];
    __syncthreads();
    int h = c >> 4, cd = c & 15;
    float rv = 0.f;
#pragma unroll
    for (int d = 0; d < 16; d++) rv += rowS[h * 16 + d] * Bw[d * 128 + h * 16 + cd];
    float ha = g_Qh[n * 128 + c] + g_agg[n * 128 + c] + rv;
    float ldv = log_deg[n];
    g_t1[n * 128 + c] = ha * (deg_coef[2 * c] + ldv * deg_coef[2 * c + 1]);
}

// ---------------- row layernorm (128 cols) ---------------------------------
__global__ void __launch_bounds__(128) ln_kernel(
    const float* __restrict__ in, const float* __restrict__ g,
    const float* __restrict__ b, float* __restrict__ out)
{
    int row = blockIdx.x, t = threadIdx.x;
    __shared__ float sred[4];
    float v = in[(size_t)row * 128 + t];
    float s = v;
#pragma unroll
    for (int o = 16; o; o >>= 1) s += __shfl_xor_sync(0xffffffffu, s, o);
    if ((t & 31) == 0) sred[t >> 5] = s;
    __syncthreads();
    float mean = (sred[0] + sred[1] + sred[2] + sred[3]) * (1.f / 128.f);
    float d = v - mean;
    __syncthreads();
    float s2 = d * d;
#pragma unroll
    for (int o = 16; o; o >>= 1) s2 += __shfl_xor_sync(0xffffffffu, s2, o);
    if ((t & 31) == 0) sred[t >> 5] = s2;
    __syncthreads();
    float var = (sred[0] + sred[1] + sred[2] + sred[3]) * (1.f / 128.f);
    out[(size_t)row * 128 + t] = d * rsqrtf(var + 1e-5f) * g[t] + b[t];
}

// ---------------- host orchestration ---------------------------------------
extern "C" void kernel_launch(void* const* d_in, const int* in_sizes, int n_in,
                              void* d_out, int out_size)
{
    const float* x        = (const float*)d_in[0];
    const float* conn     = (const float*)d_in[1];
    const float* log_deg  = (const float*)d_in[2];
    const int*   ei       = (const int*)  d_in[3];
    const float* WQ       = (const float*)d_in[4];
    const float* WK       = (const float*)d_in[5];
    const float* WV       = (const float*)d_in[6];
    const float* WE       = (const float*)d_in[7];
    const float* Aw       = (const float*)d_in[8];
    const float* Bw       = (const float*)d_in[9];
    const float* Ho_w     = (const float*)d_in[10];
    const float* Ho_b     = (const float*)d_in[11];
    const float* Eo_w     = (const float*)d_in[12];
    const float* Eo_b     = (const float*)d_in[13];
    const float* deg_coef = (const float*)d_in[14];
    const float* ln1h_g   = (const float*)d_in[15];
    const float* ln1h_b   = (const float*)d_in[16];
    const float* ln1e_g   = (const float*)d_in[17];
    const float* ln1e_b   = (const float*)d_in[18];
    const float* ln2h_g   = (const float*)d_in[19];
    const float* ln2h_b   = (const float*)d_in[20];
    const float* W1       = (const float*)d_in[21];
    const float* b1       = (const float*)d_in[22];
    const float* W2       = (const float*)d_in[23];
    const float* b2       = (const float*)d_in[24];

    const int* dstp = ei;
    const int* srcp = ei + NE;

    float* outH = (float*)d_out;
    float* outE = outH + (size_t)NND * HIDN;

    float *Qh, *Kh, *Vh, *connE, *t1, *t2, *hA, *hmid;
    cudaGetSymbolAddress((void**)&Qh, g_Qh);
    cudaGetSymbolAddress((void**)&Kh, g_Kh);
    cudaGetSymbolAddress((void**)&Vh, g_Vh);
    cudaGetSymbolAddress((void**)&connE, g_conn_e);
    cudaGetSymbolAddress((void**)&t1, g_t1);
    cudaGetSymbolAddress((void**)&t2, g_t2);
    cudaGetSymbolAddress((void**)&hA, g_hA);
    cudaGetSymbolAddress((void**)&hmid, g_hmid);

    cudaFuncSetAttribute(edge_kernelA,
                         cudaFuncAttributeMaxDynamicSharedMemorySize, 66560);

    zero_kernel<<<512, 256>>>();

    dim3 gN((NND + 127) / 128, 1);
    sgemm<false><<<gN, 256>>>(x, WQ, nullptr, nullptr, Qh, NND, 128, 128);
    sgemm<false><<<gN, 256>>>(x, WK, nullptr, nullptr, Kh, NND, 128, 128);
    sgemm<false><<<gN, 256>>>(x, WV, nullptr, nullptr, Vh, NND, 128, 128);

    edge_kernelA<<<NE / 64, 256, 66560>>>(conn, WE, Aw, dstp, srcp);
    edge_kernelB<<<(NE * 32) / 256, 256>>>(dstp, srcp);

    combine_kernel<<<NND, 128>>>(log_deg, deg_coef, Bw);

    // h path: Ho GEMM + residual x, LN1h, FFN, LN2h
    sgemm<false><<<gN, 256>>>(t1, Ho_w, Ho_b, x, t2, NND, 128, 128);
    ln_kernel<<<NND, 128>>>(t2, ln1h_g, ln1h_b, hA);
    sgemm<true ><<<dim3((NND + 127) / 128, 2), 256>>>(hA, W1, b1, nullptr, hmid, NND, 256, 128);
    sgemm<false><<<gN, 256>>>(hmid, W2, b2, hA, t2, NND, 128, 256);
    ln_kernel<<<NND, 128>>>(t2, ln2h_g, ln2h_b, outH);

    // e path: Eo GEMM + residual conn, LN1e (in place on output)
    sgemm<false><<<dim3((NE + 127) / 128, 1), 256>>>(connE, Eo_w, Eo_b, conn, outE, NE, 128, 128);
    ln_kernel<<<NE, 128>>>(outE, ln1e_g, ln1e_b, outE);
}